// round 9
// baseline (speedup 1.0000x reference)
#include <cuda_runtime.h>

#define B 8
#define M 8192
#define N 8192
#define SPLITS 64
#define ROWS (M / SPLITS)            // 128 rows per split
#define TPB 128
#define COLS_PER_BLOCK (TPB * 4)     // 512 columns per block (4 floats per thread)
#define NBLK (N / COLS_PER_BLOCK)    // 16 -> grid 16x64 = 1024 blocks

// Split-K partial sums: [SPLITS][B][N] floats = 16 MB device scratch.
__device__ float g_part[(size_t)SPLITS * B * N];

// Packed fp32x2 FMA: d = a*b + d  (sm_103a FFMA2, only reachable via PTX)
#define FMA2(d, a, b) \
    asm("fma.rn.f32x2 %0, %1, %2, %0;" : "+l"(d) : "l"(a), "l"(b))

__global__ void __launch_bounds__(TPB, 7)
snn_gemv_split(const float* __restrict__ pre,   // [B][M]
               const float* __restrict__ W)     // [M][N] row-major
{
    // Pre-spikes pre-duplicated: pre_s2[r][b] = {p, p} (64-bit), so packed
    // multipliers come straight from LDS.128. 128*8*8 = 8 KB smem.
    __shared__ unsigned long long pre_s2[ROWS][B];

    const int nb  = blockIdx.x;
    const int s   = blockIdx.y;
    const int tid = threadIdx.x;
    const int m0  = s * ROWS;

    // tid == row (ROWS == TPB == 128)
    #pragma unroll
    for (int b = 0; b < B; b++) {
        float p = pre[b * M + m0 + tid];
        float2 pp = make_float2(p, p);
        pre_s2[tid][b] = *reinterpret_cast<unsigned long long*>(&pp);
    }
    __syncthreads();

    const int n0 = nb * COLS_PER_BLOCK + tid * 4;
    const ulonglong2* Wp =
        reinterpret_cast<const ulonglong2*>(W + (size_t)m0 * N + n0);
    const size_t S16 = N / 4;        // row stride in 16-byte (ulonglong2) units

    // acc[b][0] = packed cols {0,1}, acc[b][1] = packed cols {2,3}
    unsigned long long acc[B][2];
    #pragma unroll
    for (int b = 0; b < B; b++) { acc[b][0] = 0ull; acc[b][1] = 0ull; }

    // One row of packed-FMA work; W is an ulonglong2 (4 cols as 2 packed pairs)
    #define DO_ROW(WV, MI) do {                                              \
        const ulonglong2* ps =                                               \
            reinterpret_cast<const ulonglong2*>(&pre_s2[(MI)][0]);           \
        ulonglong2 pa = ps[0];  /* batches 0,1 */                            \
        ulonglong2 pb = ps[1];  /* batches 2,3 */                            \
        ulonglong2 pc = ps[2];  /* batches 4,5 */                            \
        ulonglong2 pd = ps[3];  /* batches 6,7 */                            \
        FMA2(acc[0][0], (WV).x, pa.x); FMA2(acc[0][1], (WV).y, pa.x);        \
        FMA2(acc[1][0], (WV).x, pa.y); FMA2(acc[1][1], (WV).y, pa.y);        \
        FMA2(acc[2][0], (WV).x, pb.x); FMA2(acc[2][1], (WV).y, pb.x);        \
        FMA2(acc[3][0], (WV).x, pb.y); FMA2(acc[3][1], (WV).y, pb.y);        \
        FMA2(acc[4][0], (WV).x, pc.x); FMA2(acc[4][1], (WV).y, pc.x);        \
        FMA2(acc[5][0], (WV).x, pc.y); FMA2(acc[5][1], (WV).y, pc.y);        \
        FMA2(acc[6][0], (WV).x, pd.x); FMA2(acc[6][1], (WV).y, pd.x);        \
        FMA2(acc[7][0], (WV).x, pd.y); FMA2(acc[7][1], (WV).y, pd.y);        \
    } while (0)

    // Explicit 4-deep load batching: 4 independent LDG.128s issued in program
    // order before any FMA consumes them -> MLP >= 4 per warp.
    #pragma unroll 1
    for (int m = 0; m < ROWS; m += 4) {
        ulonglong2 w0 = Wp[(size_t)(m + 0) * S16];
        ulonglong2 w1 = Wp[(size_t)(m + 1) * S16];
        ulonglong2 w2 = Wp[(size_t)(m + 2) * S16];
        ulonglong2 w3 = Wp[(size_t)(m + 3) * S16];
        DO_ROW(w0, m + 0);
        DO_ROW(w1, m + 1);
        DO_ROW(w2, m + 2);
        DO_ROW(w3, m + 3);
    }
    #undef DO_ROW

    #pragma unroll
    for (int b = 0; b < B; b++) {
        float2 lo = *reinterpret_cast<float2*>(&acc[b][0]);
        float2 hi = *reinterpret_cast<float2*>(&acc[b][1]);
        float4 v = make_float4(lo.x, lo.y, hi.x, hi.y);
        *reinterpret_cast<float4*>(&g_part[((size_t)s * B + b) * N + n0]) = v;
    }
}

// Cooperative reduce: 8 threads per float4 output quad, 8 splits each.
// 512 blocks x 256 threads -> 131072 threads (~886/SM).
#define RTPB 256
#define QUADS_PER_BLOCK (RTPB / 8)   // 32 float4 outputs per block

__global__ void __launch_bounds__(RTPB)
snn_reduce(const float* __restrict__ thr,       // [B][N]
           const float* __restrict__ cst,       // [B][N]
           float* __restrict__ out)             // [B][N]
{
    __shared__ float4 red[RTPB];

    const int t    = threadIdx.x;
    const int ql   = t >> 3;                    // local quad 0..31
    const int k    = t & 7;                     // split group 0..7
    const int quad = blockIdx.x * QUADS_PER_BLOCK + ql;
    const int base = quad * 4;                  // float index into [B*N]

    const float4* src = reinterpret_cast<const float4*>(
        &g_part[(size_t)(k * 8) * B * N + base]);
    const size_t plane4 = (size_t)B * N / 4;    // float4 stride between splits

    // 8 independent LDG.128s as separately-named values in straight-line
    // code (the pattern that front-batched in the GEMV).
    float4 v0 = src[0 * plane4];
    float4 v1 = src[1 * plane4];
    float4 v2 = src[2 * plane4];
    float4 v3 = src[3 * plane4];
    float4 v4 = src[4 * plane4];
    float4 v5 = src[5 * plane4];
    float4 v6 = src[6 * plane4];
    float4 v7 = src[7 * plane4];

    float4 sum;
    sum.x = ((v0.x + v1.x) + (v2.x + v3.x)) + ((v4.x + v5.x) + (v6.x + v7.x));
    sum.y = ((v0.y + v1.y) + (v2.y + v3.y)) + ((v4.y + v5.y) + (v6.y + v7.y));
    sum.z = ((v0.z + v1.z) + (v2.z + v3.z)) + ((v4.z + v5.z) + (v6.z + v7.z));
    sum.w = ((v0.w + v1.w) + (v2.w + v3.w)) + ((v4.w + v5.w) + (v6.w + v7.w));

    red[t] = sum;
    __syncthreads();

    if (k == 0) {
        float4 s4 = make_float4(0.f, 0.f, 0.f, 0.f);
        #pragma unroll
        for (int j = 0; j < 8; j++) {
            float4 r = red[t + j];
            s4.x += r.x; s4.y += r.y; s4.z += r.z; s4.w += r.w;
        }

        float4 tt = *reinterpret_cast<const float4*>(&thr[base]);
        float4 cc = *reinterpret_cast<const float4*>(&cst[base]);

        float4 o;
        o.x = fminf(fmaxf(s4.x + cc.x - tt.x, 0.f), 0.9f);
        o.y = fminf(fmaxf(s4.y + cc.y - tt.y, 0.f), 0.9f);
        o.z = fminf(fmaxf(s4.z + cc.z - tt.z, 0.f), 0.9f);
        o.w = fminf(fmaxf(s4.w + cc.w - tt.w, 0.f), 0.9f);

        *reinterpret_cast<float4*>(&out[base]) = o;
    }
}

extern "C" void kernel_launch(void* const* d_in, const int* in_sizes, int n_in,
                              void* d_out, int out_size)
{
    const float* pre = (const float*)d_in[0];   // pre_spikes [8,1,8192]
    const float* W   = (const float*)d_in[1];   // W [8192,8192]
    const float* thr = (const float*)d_in[2];   // thr [8,1,8192]
    const float* cst = (const float*)d_in[3];   // const_inp [8,1,8192]
    float* out = (float*)d_out;                 // [8,1,8192]

    dim3 grid(NBLK, SPLITS);                    // 16 x 64 = 1024 blocks
    snn_gemv_split<<<grid, TPB>>>(pre, W);

    // 16384 quads * 8 threads = 131072 threads -> 512 blocks
    snn_reduce<<<(B * N * 8) / (RTPB * 4), RTPB>>>(thr, cst, out);
}

// round 10
// speedup vs baseline: 1.1295x; 1.1295x over previous
#include <cuda_runtime.h>

#define B 8
#define M 8192
#define N 8192
#define SPLITS 64
#define ROWS (M / SPLITS)            // 128 rows per split
#define TPB 128
#define COLS_PER_BLOCK (TPB * 4)     // 512 columns per block (4 floats per thread)
#define NBLK (N / COLS_PER_BLOCK)    // 16 -> grid 16x64 = 1024 blocks

// Split-K partial sums: [SPLITS][B][N] floats = 16 MB device scratch.
// This FITS in the 126 MB L2 -- provided the streaming W reads don't evict it.
__device__ float g_part[(size_t)SPLITS * B * N];

// Packed fp32x2 FMA: d = a*b + d  (sm_103a FFMA2, only reachable via PTX)
#define FMA2(d, a, b) \
    asm("fma.rn.f32x2 %0, %1, %2, %0;" : "+l"(d) : "l"(a), "l"(b))

__global__ void __launch_bounds__(TPB, 7)
snn_gemv_split(const float* __restrict__ pre,   // [B][M]
               const float* __restrict__ W)     // [M][N] row-major
{
    // Pre-spikes pre-duplicated: pre_s2[r][b] = {p, p} (64-bit), so packed
    // multipliers come straight from LDS.128. 128*8*8 = 8 KB smem.
    __shared__ unsigned long long pre_s2[ROWS][B];

    const int nb  = blockIdx.x;
    const int s   = blockIdx.y;
    const int tid = threadIdx.x;
    const int m0  = s * ROWS;

    // tid == row (ROWS == TPB == 128)
    #pragma unroll
    for (int b = 0; b < B; b++) {
        float p = pre[b * M + m0 + tid];
        float2 pp = make_float2(p, p);
        pre_s2[tid][b] = *reinterpret_cast<unsigned long long*>(&pp);
    }
    __syncthreads();

    const int n0 = nb * COLS_PER_BLOCK + tid * 4;
    const float4* Wp = reinterpret_cast<const float4*>(W + (size_t)m0 * N + n0);
    const size_t S4 = N / 4;         // row stride in float4 (16 B) units

    // acc[b][0] = packed cols {0,1}, acc[b][1] = packed cols {2,3}
    unsigned long long acc[B][2];
    #pragma unroll
    for (int b = 0; b < B; b++) { acc[b][0] = 0ull; acc[b][1] = 0ull; }

    // One row of packed-FMA work; WV is a float4 reinterpreted as 2 packed pairs
    #define DO_ROW(WV, MI) do {                                              \
        ulonglong2 wv = *reinterpret_cast<ulonglong2*>(&(WV));               \
        const ulonglong2* ps =                                               \
            reinterpret_cast<const ulonglong2*>(&pre_s2[(MI)][0]);           \
        ulonglong2 pa = ps[0];  /* batches 0,1 */                            \
        ulonglong2 pb = ps[1];  /* batches 2,3 */                            \
        ulonglong2 pc = ps[2];  /* batches 4,5 */                            \
        ulonglong2 pd = ps[3];  /* batches 6,7 */                            \
        FMA2(acc[0][0], wv.x, pa.x); FMA2(acc[0][1], wv.y, pa.x);            \
        FMA2(acc[1][0], wv.x, pa.y); FMA2(acc[1][1], wv.y, pa.y);            \
        FMA2(acc[2][0], wv.x, pb.x); FMA2(acc[2][1], wv.y, pb.x);            \
        FMA2(acc[3][0], wv.x, pb.y); FMA2(acc[3][1], wv.y, pb.y);            \
        FMA2(acc[4][0], wv.x, pc.x); FMA2(acc[4][1], wv.y, pc.x);            \
        FMA2(acc[5][0], wv.x, pc.y); FMA2(acc[5][1], wv.y, pc.y);            \
        FMA2(acc[6][0], wv.x, pd.x); FMA2(acc[6][1], wv.y, pd.x);            \
        FMA2(acc[7][0], wv.x, pd.y); FMA2(acc[7][1], wv.y, pd.y);            \
    } while (0)

    // Explicit 4-deep load batching, with .CS streaming hint (evict-first in
    // L2) so the one-shot W stream does NOT evict the L2-resident partials.
    #pragma unroll 1
    for (int m = 0; m < ROWS; m += 4) {
        float4 w0 = __ldcs(Wp + (size_t)(m + 0) * S4);
        float4 w1 = __ldcs(Wp + (size_t)(m + 1) * S4);
        float4 w2 = __ldcs(Wp + (size_t)(m + 2) * S4);
        float4 w3 = __ldcs(Wp + (size_t)(m + 3) * S4);
        DO_ROW(w0, m + 0);
        DO_ROW(w1, m + 1);
        DO_ROW(w2, m + 2);
        DO_ROW(w3, m + 3);
    }
    #undef DO_ROW

    #pragma unroll
    for (int b = 0; b < B; b++) {
        float2 lo = *reinterpret_cast<float2*>(&acc[b][0]);
        float2 hi = *reinterpret_cast<float2*>(&acc[b][1]);
        float4 v = make_float4(lo.x, lo.y, hi.x, hi.y);
        *reinterpret_cast<float4*>(&g_part[((size_t)s * B + b) * N + n0]) = v;
    }
}

__global__ void __launch_bounds__(256)
snn_reduce(const float* __restrict__ thr,       // [B][N]
           const float* __restrict__ cst,       // [B][N]
           float* __restrict__ out)             // [B][N]
{
    const int idx = blockIdx.x * 256 + threadIdx.x;   // over B*N (65536)

    float sum = 0.f;
    #pragma unroll
    for (int s = 0; s < SPLITS; s++)
        sum += g_part[(size_t)s * B * N + idx];       // L2-resident reads

    float o = sum + cst[idx] - thr[idx];
    out[idx] = fminf(fmaxf(o, 0.f), 0.9f);
}

extern "C" void kernel_launch(void* const* d_in, const int* in_sizes, int n_in,
                              void* d_out, int out_size)
{
    const float* pre = (const float*)d_in[0];   // pre_spikes [8,1,8192]
    const float* W   = (const float*)d_in[1];   // W [8192,8192]
    const float* thr = (const float*)d_in[2];   // thr [8,1,8192]
    const float* cst = (const float*)d_in[3];   // const_inp [8,1,8192]
    float* out = (float*)d_out;                 // [8,1,8192]

    dim3 grid(NBLK, SPLITS);                    // 16 x 64 = 1024 blocks
    snn_gemv_split<<<grid, TPB>>>(pre, W);

    snn_reduce<<<(B * N) / 256, 256>>>(thr, cst, out);
}